// round 14
// baseline (speedup 1.0000x reference)
#include <cuda_runtime.h>

#define BB 2
#define NN 4096
#define MM 1024
#define KK1 32
#define KK2 16

// packed f32x2 helpers (sm_103a) — PTX forms from ptx_helpers.cuh (R9/R13-validated)
#define MUL_F32X2(out, a, b) asm("mul.rn.f32x2 %0, %1, %2;" : "=l"(out) : "l"(a), "l"(b))
#define ADD_F32X2(out, a, b) asm("add.rn.f32x2 %0, %1, %2;" : "=l"(out) : "l"(a), "l"(b))
#define PACK_F32X2(out, lo, hi) asm("mov.b64 %0, {%1, %2};" : "=l"(out) : "r"(lo), "r"(hi))
#define UNPACK_F32X2(lo, hi, in) asm("mov.b64 {%0, %1}, %2;" : "=r"(lo), "=r"(hi) : "l"(in))

// ---- scratch (device globals; no allocations allowed) ----
__device__ int   d_cidx[BB*MM];
__device__ float d_nxyz[BB*MM*3];
__device__ int   d_ncomp[BB*MM];
__device__ float d_feat1[BB*NN*64];
__device__ int   d_idx1[BB*MM*KK1];
__device__ int   d_idx2[BB*MM*KK2];
__device__ float d_center[BB*MM*64];
__device__ float d_cfea1[BB*MM*96];
__device__ float d_gfea1[BB*MM*96];
__device__ float d_cfea2[BB*MM*128];
__device__ float d_gfea2[BB*MM*128];
__device__ float d_lpf[BB*MM*128];

__device__ __forceinline__ float sqdist(float ax, float ay, float az,
                                        float bx, float by, float bz) {
    // bit-exact vs reference: no FMA contraction, (dx^2+dy^2)+dz^2 order
    float dx = __fsub_rn(ax, bx), dy = __fsub_rn(ay, by), dz = __fsub_rn(az, bz);
    return __fadd_rn(__fadd_rn(__fmul_rn(dx, dx), __fmul_rn(dy, dy)), __fmul_rn(dz, dz));
}

// tiny no-op kernel: shifts the profiled-launch slot
__global__ void nop_kernel() {}

// ===== FPS (+fused gather): 512 thr, 8 pts/thr, f32x2, two-level REDUX ======
// Packed per-lane .rn math ≡ scalar path (R9/R13-validated). 16-warp masked
// level-2 REDUX = R4-R8-validated shape. First-match chain ≡ strict-> scan.
__global__ void __launch_bounds__(512) fps_kernel(const float* __restrict__ xyz,
                                                  const int* __restrict__ comp,
                                                  float* __restrict__ out) {
    extern __shared__ float4 sP[];               // 4096 points, 64KB
    __shared__ unsigned sD[2][16], sI[2][16];
    __shared__ int sCid[MM];
    int b = blockIdx.x;
    const float* X = xyz + b * NN * 3;
    int tid = threadIdx.x, lane = tid & 31, w = tid >> 5;

    unsigned long long pxp[4], pyp[4], pzp[4];
    float dd[8];
#pragma unroll
    for (int r2 = 0; r2 < 4; r2++) {
        int i0 = tid + ((2*r2) << 9), i1 = tid + ((2*r2+1) << 9);
        float x0 = X[3*i0], y0 = X[3*i0+1], z0 = X[3*i0+2];
        float x1 = X[3*i1], y1 = X[3*i1+1], z1 = X[3*i1+2];
        PACK_F32X2(pxp[r2], __float_as_uint(x0), __float_as_uint(x1));
        PACK_F32X2(pyp[r2], __float_as_uint(y0), __float_as_uint(y1));
        PACK_F32X2(pzp[r2], __float_as_uint(z0), __float_as_uint(z1));
        sP[i0] = make_float4(x0, y0, z0, 0.f);
        sP[i1] = make_float4(x1, y1, z1, 0.f);
        dd[2*r2] = 1e10f; dd[2*r2+1] = 1e10f;
    }
    __syncthreads();
    float lx = X[0], ly = X[1], lz = X[2];
    if (tid == 0) { d_cidx[b*MM] = 0; sCid[0] = 0; }

    for (int it = 1; it < MM; it++) {
        unsigned long long lx2, ly2, lz2;
        unsigned nx = __float_as_uint(-lx), ny = __float_as_uint(-ly), nz = __float_as_uint(-lz);
        PACK_F32X2(lx2, nx, nx);
        PACK_F32X2(ly2, ny, ny);
        PACK_F32X2(lz2, nz, nz);
#pragma unroll
        for (int r2 = 0; r2 < 4; r2++) {
            unsigned long long dx, dy, dz, s, t;
            ADD_F32X2(dx, pxp[r2], lx2);      // p - l (exact: x + (-lx))
            MUL_F32X2(s,  dx, dx);
            ADD_F32X2(dy, pyp[r2], ly2);
            MUL_F32X2(t,  dy, dy);
            ADD_F32X2(s,  s, t);
            ADD_F32X2(dz, pzp[r2], lz2);
            MUL_F32X2(t,  dz, dz);
            ADD_F32X2(s,  s, t);
            unsigned u0, u1; UNPACK_F32X2(u0, u1, s);
            dd[2*r2]   = fminf(dd[2*r2],   __uint_as_float(u0));
            dd[2*r2+1] = fminf(dd[2*r2+1], __uint_as_float(u1));
        }
        // per-thread argmax: max tree + first-match scan (lowest r = lowest idx)
        float m01 = fmaxf(dd[0], dd[1]), m23 = fmaxf(dd[2], dd[3]);
        float m45 = fmaxf(dd[4], dd[5]), m67 = fmaxf(dd[6], dd[7]);
        float bd = fmaxf(fmaxf(m01, m23), fmaxf(m45, m67));
        unsigned bi = (dd[0] == bd) ? (unsigned)tid
                    : (dd[1] == bd) ? (unsigned)(tid + 512)
                    : (dd[2] == bd) ? (unsigned)(tid + 1024)
                    : (dd[3] == bd) ? (unsigned)(tid + 1536)
                    : (dd[4] == bd) ? (unsigned)(tid + 2048)
                    : (dd[5] == bd) ? (unsigned)(tid + 2560)
                    : (dd[6] == bd) ? (unsigned)(tid + 3072)
                    :                 (unsigned)(tid + 3584);
        unsigned d32 = __float_as_uint(bd);                     // nonneg floats order as uints
        unsigned wd  = __reduce_max_sync(0xffffffffu, d32);
        unsigned ic  = (d32 == wd) ? bi : 0xffffffffu;
        unsigned wi  = __reduce_min_sync(0xffffffffu, ic);
        int buf = it & 1;
        if (lane == 0) { sD[buf][w] = wd; sI[buf][w] = wi; }
        __syncthreads();
        unsigned td = (lane < 16) ? sD[buf][lane] : 0u;
        unsigned gd = __reduce_max_sync(0xffffffffu, td);
        unsigned ti = (lane < 16 && td == gd) ? sI[buf][lane] : 0xffffffffu;
        unsigned gi = __reduce_min_sync(0xffffffffu, ti);
        if (tid == 0) d_cidx[b*MM + it] = (int)gi;
        if (tid == (it & 511)) sCid[it] = (int)gi;   // covers it and it+512
        float4 p = sP[gi];
        lx = p.x; ly = p.y; lz = p.z;
    }

    // fused gather: 512 threads emit 2 sampled points each
    __syncthreads();
#pragma unroll
    for (int h = 0; h < 2; h++) {
        int m = tid + (h << 9);
        int ci = sCid[m];
        float4 p = sP[ci];
        int g = b*MM + m;
        d_nxyz[g*3+0] = p.x; d_nxyz[g*3+1] = p.y; d_nxyz[g*3+2] = p.z;
        out[g*3+0] = p.x; out[g*3+1] = p.y; out[g*3+2] = p.z;    // new_xyz
        int cp = comp[b*NN + ci];
        d_ncomp[g] = cp;
        out[BB*MM*3 + BB*256*MM + g] = (float)cp;                 // new_comp
    }
}

// ================= feat1 = ReLU(features @ W1d^T + b) ========================
__global__ void __launch_bounds__(256) feat1_kernel(const float* __restrict__ F,
                                                    const float* __restrict__ W,
                                                    const float* __restrict__ bias) {
    __shared__ float sf[4][64];
    __shared__ float sw[64 * 65];
    int p0 = blockIdx.x << 2;
    int tid = threadIdx.x;
    for (int i = tid; i < 4096; i += 256) sw[(i >> 6) * 65 + (i & 63)] = W[i];
    { int p = tid >> 6, j = tid & 63; sf[p][j] = F[(p0 + p) * 64 + j]; }
    __syncthreads();
    int c = tid & 63, p = tid >> 6;
    float acc = bias[c];
#pragma unroll
    for (int j = 0; j < 64; j++) acc += sf[p][j] * sw[c * 65 + j];
    d_feat1[(p0 + p) * 64 + c] = fmaxf(acc, 0.f);
}

// ==== knn1: 32-NN among 4096 — winner-only rescan + REDUX (R8-proven) =======
__global__ void __launch_bounds__(256) knn1_kernel(const float* __restrict__ xyz) {
    int g = blockIdx.x, b = g >> 10;
    int tid = threadIdx.x, lane = tid & 31, w = tid >> 5;
    __shared__ unsigned sD[2][8], sI[2][8];
    const float* X = xyz + b * NN * 3;
    float qx = d_nxyz[g*3+0], qy = d_nxyz[g*3+1], qz = d_nxyz[g*3+2];

    unsigned long long k[16];
#pragma unroll
    for (int r = 0; r < 16; r++) {
        int i = tid + (r << 8);
        float d = sqdist(qx, qy, qz, X[3*i], X[3*i+1], X[3*i+2]);
        k[r] = ((unsigned long long)__float_as_uint(d) << 32) | (unsigned)(i + 1);  // keys > 0
    }
    unsigned long long cand = ~0ull;
#pragma unroll
    for (int r = 0; r < 16; r++)
        if (k[r] < cand) cand = k[r];

    for (int sel = 0; sel < KK1; sel++) {
        unsigned d32 = (unsigned)(cand >> 32);
        unsigned wd  = __reduce_min_sync(0xffffffffu, d32);
        unsigned ic  = (d32 == wd) ? (unsigned)cand : 0xffffffffu;
        unsigned wi  = __reduce_min_sync(0xffffffffu, ic);
        int buf = sel & 1;
        if (lane == 0) { sD[buf][w] = wd; sI[buf][w] = wi; }
        __syncthreads();
        unsigned td = (lane < 8) ? sD[buf][lane] : 0xffffffffu;
        unsigned bd = __reduce_min_sync(0xffffffffu, td);
        unsigned ti = (lane < 8 && td == bd) ? sI[buf][lane] : 0xffffffffu;
        unsigned bi = __reduce_min_sync(0xffffffffu, ti);
        if (tid == 0) d_idx1[g*KK1 + sel] = (int)bi - 1;
        unsigned long long winner = ((unsigned long long)bd << 32) | bi;
        if (cand == winner) {           // exactly one thread (keys unique)
            cand = ~0ull;
#pragma unroll
            for (int r = 0; r < 16; r++)
                if (k[r] > winner && k[r] < cand) cand = k[r];
        }
    }
}

// ==== knn2: comp-constrained 16-NN — winner-only rescan (R8-proven) =========
__global__ void __launch_bounds__(256) knn2_kernel() {
    int g = blockIdx.x, b = g >> 10;
    int tid = threadIdx.x, lane = tid & 31, w = tid >> 5;
    __shared__ unsigned sD[2][8], sI[2][8];
    const float* RX = d_nxyz + b * MM * 3;
    const int* RC = d_ncomp + b * MM;
    float qx = d_nxyz[g*3+0], qy = d_nxyz[g*3+1], qz = d_nxyz[g*3+2];
    int qc = d_ncomp[g];

    unsigned long long k[4];
#pragma unroll
    for (int r = 0; r < 4; r++) {
        int i = tid + (r << 8);
        float d = sqdist(qx, qy, qz, RX[3*i], RX[3*i+1], RX[3*i+2]);
        if (RC[i] != qc) d = __fadd_rn(d, 1e9f);
        k[r] = ((unsigned long long)__float_as_uint(d) << 32) | (unsigned)(i + 1);  // keys > 0
    }
    unsigned long long cand = ~0ull;
#pragma unroll
    for (int r = 0; r < 4; r++)
        if (k[r] < cand) cand = k[r];

    for (int sel = 0; sel < KK2; sel++) {
        unsigned d32 = (unsigned)(cand >> 32);
        unsigned wd  = __reduce_min_sync(0xffffffffu, d32);
        unsigned ic  = (d32 == wd) ? (unsigned)cand : 0xffffffffu;
        unsigned wi  = __reduce_min_sync(0xffffffffu, ic);
        int buf = sel & 1;
        if (lane == 0) { sD[buf][w] = wd; sI[buf][w] = wi; }
        __syncthreads();
        unsigned td = (lane < 8) ? sD[buf][lane] : 0xffffffffu;
        unsigned bd = __reduce_min_sync(0xffffffffu, td);
        unsigned ti = (lane < 8 && td == bd) ? sI[buf][lane] : 0xffffffffu;
        unsigned bi = __reduce_min_sync(0xffffffffu, ti);
        if (tid == 0) d_idx2[g*KK2 + sel] = (int)bi - 1;
        unsigned long long winner = ((unsigned long long)bd << 32) | bi;
        if (cand == winner) {
            cand = ~0ull;
#pragma unroll
            for (int r = 0; r < 4; r++)
                if (k[r] > winner && k[r] < cand) cand = k[r];
        }
    }
}

// ===== stage 1: weights [j][o] stride 97; s_w padded to 16B multiple ========
__global__ void __launch_bounds__(96) stage1_kernel(
    const float* __restrict__ xyz,
    const float* __restrict__ Wdx1, const float* __restrict__ bdx1,
    const float* __restrict__ Ww1,  const float* __restrict__ bw1) {
    int g = blockIdx.x, b = g >> 10, tid = threadIdx.x;
    __shared__ float s_w[6500];                      // 67*97=6499, +1 pad -> 26000 B (16B mult)
    __shared__ __align__(16) float s_in[67*36];      // [j][k], float4-read rows
    __shared__ float s_c[64];
    __shared__ int s_idx[KK1];
    __shared__ float s_q[3];

    for (int e = tid; e < 96*67; e += 96) { int o = e/67, j = e - o*67; s_w[j*97+o] = Ww1[e]; }
    if (tid < KK1) s_idx[tid] = d_idx1[g*KK1 + tid];
    if (tid < 3)   s_q[tid] = d_nxyz[g*3 + tid];
    if (tid >= 32 && tid < 96) {
        int c = tid - 32;
        float cv = d_feat1[(b*NN + d_cidx[g]) * 64 + c];
        s_c[c] = cv;
        d_center[g*64 + c] = cv;
    }
    __syncthreads();
    for (int e = tid; e < 2048; e += 96) {
        int k = e >> 6, c = e & 63;
        s_in[(3+c)*36 + k] = d_feat1[(b*NN + s_idx[k]) * 64 + c] - s_c[c];
    }
    if (tid < KK1) {
        int gi = s_idx[tid];
        s_in[0*36 + tid] = xyz[(b*NN+gi)*3+0] - s_q[0];
        s_in[1*36 + tid] = xyz[(b*NN+gi)*3+1] - s_q[1];
        s_in[2*36 + tid] = xyz[(b*NN+gi)*3+2] - s_q[2];
    }
    __syncthreads();

    int o = tid;
    float a[KK1];
    float bv = bw1[o];
#pragma unroll
    for (int k = 0; k < KK1; k++) a[k] = bv;
    for (int j = 0; j < 67; j++) {
        float wv = s_w[j*97 + o];
        const float4* row = (const float4*)&s_in[j*36];
#pragma unroll
        for (int q = 0; q < 8; q++) {
            float4 v = row[q];
            a[4*q+0] += v.x*wv; a[4*q+1] += v.y*wv;
            a[4*q+2] += v.z*wv; a[4*q+3] += v.w*wv;
        }
    }
    float mx = 0.f;
#pragma unroll
    for (int k = 0; k < KK1; k++) { a[k] = fmaxf(a[k], 0.f); mx = fmaxf(mx, a[k]); }
    d_cfea1[g*96 + o] = mx;
    float se = 0.f;
#pragma unroll
    for (int k = 0; k < KK1; k++) { a[k] = __expf(a[k] - mx); se += a[k]; }
    float res = 0.f;
    if (o < 32) {
        float w0 = Wdx1[o*3], w1 = Wdx1[o*3+1], w2 = Wdx1[o*3+2], bb = bdx1[o];
#pragma unroll
        for (int k = 0; k < KK1; k++) {
            float val = fmaxf(s_in[k]*w0 + s_in[36+k]*w1 + s_in[72+k]*w2 + bb, 0.f);
            res += val * a[k];
        }
    } else {
        int c = o - 32;
#pragma unroll
        for (int k = 0; k < KK1; k++) res += (s_in[(3+c)*36 + k] + s_c[c]) * a[k];
    }
    d_gfea1[g*96 + o] = __fdividef(res, se);
}

// ===== stage 2: weights [j][o] stride 129, region padded for alignment ======
#define S2W 12772   // 99*129 = 12771, padded: 51088 B, 16B multiple
__global__ void __launch_bounds__(128) stage2_kernel(
    const float* __restrict__ Wdx2, const float* __restrict__ bdx2,
    const float* __restrict__ Ww2,  const float* __restrict__ bw2) {
    int g = blockIdx.x, b = g >> 10, tid = threadIdx.x;
    extern __shared__ float sm2[];
    float* s_w  = sm2;            // [99][129]
    float* s_in = sm2 + S2W;      // [99][20], 16B-aligned
    __shared__ float s_c[96];
    __shared__ int s_idx[KK2];
    __shared__ float s_q[3];

    for (int e = tid; e < 128*99; e += 128) { int o = e/99, j = e - o*99; s_w[j*129+o] = Ww2[e]; }
    if (tid < KK2) s_idx[tid] = d_idx2[g*KK2 + tid];
    if (tid < 3)   s_q[tid] = d_nxyz[g*3 + tid];
    if (tid < 96)  s_c[tid] = d_gfea1[g*96 + tid];
    __syncthreads();
    for (int e = tid; e < KK2*96; e += 128) {
        int k = e / 96, c = e - k*96;
        s_in[c*20 + k] = d_gfea1[((b<<10) + s_idx[k]) * 96 + c] - s_c[c];
    }
    if (tid < KK2) {
        int gi = (b<<10) + s_idx[tid];
        s_in[96*20 + tid] = d_nxyz[gi*3+0] - s_q[0];
        s_in[97*20 + tid] = d_nxyz[gi*3+1] - s_q[1];
        s_in[98*20 + tid] = d_nxyz[gi*3+2] - s_q[2];
    }
    __syncthreads();

    int o = tid;
    float a[KK2];
    float bv = bw2[o];
#pragma unroll
    for (int k = 0; k < KK2; k++) a[k] = bv;
    for (int j = 0; j < 99; j++) {
        float wv = s_w[j*129 + o];
        const float4* row = (const float4*)&s_in[j*20];
#pragma unroll
        for (int q = 0; q < 4; q++) {
            float4 v = row[q];
            a[4*q+0] += v.x*wv; a[4*q+1] += v.y*wv;
            a[4*q+2] += v.z*wv; a[4*q+3] += v.w*wv;
        }
    }
    float mx = 0.f;
#pragma unroll
    for (int k = 0; k < KK2; k++) { a[k] = fmaxf(a[k], 0.f); mx = fmaxf(mx, a[k]); }
    d_cfea2[g*128 + o] = mx;
    float se = 0.f;
#pragma unroll
    for (int k = 0; k < KK2; k++) { a[k] = __expf(a[k] - mx); se += a[k]; }
    float res = 0.f;
    if (o < 32) {
        float w0 = Wdx2[o*3], w1 = Wdx2[o*3+1], w2 = Wdx2[o*3+2], bb = bdx2[o];
#pragma unroll
        for (int k = 0; k < KK2; k++) {
            float val = fmaxf(s_in[96*20+k]*w0 + s_in[97*20+k]*w1 + s_in[98*20+k]*w2 + bb, 0.f);
            res += val * a[k];
        }
    } else {
        int c = o - 32;
#pragma unroll
        for (int k = 0; k < KK2; k++) res += (s_in[c*20 + k] + s_c[c]) * a[k];
    }
    d_gfea2[g*128 + o] = __fdividef(res, se);
}

// ===== stage 3b: weights [j][o] stride 129; max-pool only (idx3 == idx2) ====
#define S3W 16900   // 131*129 = 16899, padded: 67600 B, 16B multiple
__global__ void __launch_bounds__(128) stage3b_kernel(
    const float* __restrict__ Wsp3, const float* __restrict__ bsp3) {
    int g = blockIdx.x, b = g >> 10, tid = threadIdx.x;
    extern __shared__ float sm3[];
    float* s_w  = sm3;                // [131][129]
    float* s_in = sm3 + S3W;          // [131][20], 16B-aligned
    __shared__ float s_c[128];
    __shared__ int s_idx[KK2];
    __shared__ float s_q[3];

    for (int e = tid; e < 128*131; e += 128) { int o = e/131, j = e - o*131; s_w[j*129+o] = Wsp3[e]; }
    if (tid < KK2) s_idx[tid] = d_idx2[g*KK2 + tid];
    if (tid < 3)   s_q[tid] = d_nxyz[g*3 + tid];
    s_c[tid] = d_gfea2[g*128 + tid];
    __syncthreads();
    for (int e = tid; e < KK2*128; e += 128) {
        int k = e >> 7, c = e & 127;
        s_in[c*20 + k] = d_gfea2[((b<<10) + s_idx[k]) * 128 + c] - s_c[c];
    }
    if (tid < KK2) {
        int gi = (b<<10) + s_idx[tid];
        s_in[128*20 + tid] = d_nxyz[gi*3+0] - s_q[0];
        s_in[129*20 + tid] = d_nxyz[gi*3+1] - s_q[1];
        s_in[130*20 + tid] = d_nxyz[gi*3+2] - s_q[2];
    }
    __syncthreads();

    int o = tid;
    float a[KK2];
    float bv = bsp3[o];
#pragma unroll
    for (int k = 0; k < KK2; k++) a[k] = bv;
    for (int j = 0; j < 131; j++) {
        float wv = s_w[j*129 + o];
        const float4* row = (const float4*)&s_in[j*20];
#pragma unroll
        for (int q = 0; q < 4; q++) {
            float4 v = row[q];
            a[4*q+0] += v.x*wv; a[4*q+1] += v.y*wv;
            a[4*q+2] += v.z*wv; a[4*q+3] += v.w*wv;
        }
    }
    float mx = 0.f;
#pragma unroll
    for (int k = 0; k < KK2; k++) mx = fmaxf(mx, fmaxf(a[k], 0.f));
    d_lpf[g*128 + o] = mx;
}

// ================= final: ReLU(concat(768) @ Wnew^T + bnew) -> (B,256,M) =====
__global__ void __launch_bounds__(256) final_kernel(const float* __restrict__ Wnew,
                                                    const float* __restrict__ bnew,
                                                    float* __restrict__ out) {
    int g0 = blockIdx.x * 8;
    int tid = threadIdx.x;
    __shared__ float XT[768*8];   // [j][p]
    for (int e = tid; e < 8*128; e += 256) {
        int p = e >> 7, c = e & 127, g = g0 + p;
        float v = d_cfea2[g*128 + c];
        XT[c*8 + p] = v;                    // g_fea3 == c_fea2
        XT[(384+c)*8 + p] = v;              // c_fea2
        XT[(128+c)*8 + p] = d_lpf[g*128 + c];
        XT[(256+c)*8 + p] = d_gfea2[g*128 + c];
    }
    for (int e = tid; e < 8*96; e += 256) {
        int p = e / 96, c = e - p*96, g = g0 + p;
        XT[(512+c)*8 + p] = d_gfea1[g*96 + c];
        XT[(608+c)*8 + p] = d_cfea1[g*96 + c];
    }
    for (int e = tid; e < 8*64; e += 256) {
        int p = e >> 6, c = e & 63, g = g0 + p;
        XT[(704+c)*8 + p] = d_center[g*64 + c];
    }
    __syncthreads();

    int o = tid;
    float acc[8];
    float bv = bnew[o];
#pragma unroll
    for (int p = 0; p < 8; p++) acc[p] = bv;
    const float* wr = Wnew + o*768;
#pragma unroll 4
    for (int j = 0; j < 768; j++) {
        float wv = __ldg(wr + j);
        float4 v0 = *(const float4*)&XT[j*8];
        float4 v1 = *(const float4*)&XT[j*8 + 4];
        acc[0] += v0.x*wv; acc[1] += v0.y*wv; acc[2] += v0.z*wv; acc[3] += v0.w*wv;
        acc[4] += v1.x*wv; acc[5] += v1.y*wv; acc[6] += v1.z*wv; acc[7] += v1.w*wv;
    }
#pragma unroll
    for (int p = 0; p < 8; p++) {
        int g = g0 + p, b = g >> 10, m = g & 1023;
        out[BB*MM*3 + b*256*MM + o*MM + m] = fmaxf(acc[p], 0.f);
    }
}

extern "C" void kernel_launch(void* const* d_in, const int* in_sizes, int n_in,
                              void* d_out, int out_size) {
    const float* xyz      = (const float*)d_in[0];
    const float* features = (const float*)d_in[1];
    const int*   comp     = (const int*)d_in[2];
    const float* W1d  = (const float*)d_in[3];
    const float* b1d  = (const float*)d_in[4];
    const float* Wdx1 = (const float*)d_in[5];
    const float* bdx1 = (const float*)d_in[6];
    const float* Ww1  = (const float*)d_in[7];
    const float* bw1  = (const float*)d_in[8];
    const float* Wdx2 = (const float*)d_in[9];
    const float* bdx2 = (const float*)d_in[10];
    const float* Ww2  = (const float*)d_in[11];
    const float* bw2  = (const float*)d_in[12];
    // d_in[13], d_in[14] = Ww3, bw3 — unused (stage-3 attention is the identity)
    const float* Wsp3 = (const float*)d_in[15];
    const float* bsp3 = (const float*)d_in[16];
    const float* Wnew = (const float*)d_in[17];
    const float* bnew = (const float*)d_in[18];
    float* out = (float*)d_out;

    static const int SMF = NN * 16;                      // 65536 B (fps coords)
    static const int SM2 = (S2W + 99*20) * 4;            // 59008 B
    static const int SM3 = (S3W + 131*20) * 4;           // 78080 B
    cudaFuncSetAttribute(fps_kernel,     cudaFuncAttributeMaxDynamicSharedMemorySize, SMF);
    cudaFuncSetAttribute(stage2_kernel,  cudaFuncAttributeMaxDynamicSharedMemorySize, SM2);
    cudaFuncSetAttribute(stage3b_kernel, cudaFuncAttributeMaxDynamicSharedMemorySize, SM3);

    // launch order puts knn2 4th -> it lands in the ncu capture window
    feat1_kernel<<<BB*NN/4, 256>>>(features, W1d, b1d);   // independent of fps
    fps_kernel<<<BB, 512, SMF>>>(xyz, comp, out);         // includes fused gather
    nop_kernel<<<1, 32>>>();
    knn2_kernel<<<BB*MM, 256>>>();                        // profiled this round
    knn1_kernel<<<BB*MM, 256>>>(xyz);
    stage1_kernel<<<BB*MM, 96>>>(xyz, Wdx1, bdx1, Ww1, bw1);
    stage2_kernel<<<BB*MM, 128, SM2>>>(Wdx2, bdx2, Ww2, bw2);
    stage3b_kernel<<<BB*MM, 128, SM3>>>(Wsp3, bsp3);
    final_kernel<<<BB*MM/8, 256>>>(Wnew, bnew, out);
}

// round 15
// speedup vs baseline: 1.1232x; 1.1232x over previous
#include <cuda_runtime.h>

#define BB 2
#define NN 4096
#define MM 1024
#define KK1 32
#define KK2 16

// packed f32x2 helpers (sm_103a) — PTX forms from ptx_helpers.cuh (R9/R13-validated)
#define MUL_F32X2(out, a, b) asm("mul.rn.f32x2 %0, %1, %2;" : "=l"(out) : "l"(a), "l"(b))
#define ADD_F32X2(out, a, b) asm("add.rn.f32x2 %0, %1, %2;" : "=l"(out) : "l"(a), "l"(b))
#define PACK_F32X2(out, lo, hi) asm("mov.b64 %0, {%1, %2};" : "=l"(out) : "r"(lo), "r"(hi))
#define UNPACK_F32X2(lo, hi, in) asm("mov.b64 {%0, %1}, %2;" : "=r"(lo), "=r"(hi) : "l"(in))

// ---- scratch (device globals; no allocations allowed) ----
__device__ int   d_cidx[BB*MM];
__device__ float d_nxyz[BB*MM*3];
__device__ int   d_ncomp[BB*MM];
__device__ float d_feat1[BB*NN*64];
__device__ int   d_idx1[BB*MM*KK1];
__device__ int   d_idx2[BB*MM*KK2];
__device__ float d_center[BB*MM*64];
__device__ float d_cfea1[BB*MM*96];
__device__ float d_gfea1[BB*MM*96];
__device__ float d_cfea2[BB*MM*128];
__device__ float d_gfea2[BB*MM*128];
__device__ float d_lpf[BB*MM*128];

__device__ __forceinline__ float sqdist(float ax, float ay, float az,
                                        float bx, float by, float bz) {
    // bit-exact vs reference: no FMA contraction, (dx^2+dy^2)+dz^2 order
    float dx = __fsub_rn(ax, bx), dy = __fsub_rn(ay, by), dz = __fsub_rn(az, bz);
    return __fadd_rn(__fadd_rn(__fmul_rn(dx, dx), __fmul_rn(dy, dy)), __fmul_rn(dz, dz));
}

// ======== FPS (+fused gather): 1024 thr, 4 pts/thr, f32x2 + REDUX argmax ====
// R13-proven: 347us, bit-exact.
__global__ void __launch_bounds__(1024) fps_kernel(const float* __restrict__ xyz,
                                                   const int* __restrict__ comp,
                                                   float* __restrict__ out) {
    extern __shared__ float4 sP[];               // 4096 points, 64KB
    __shared__ unsigned sD[2][32], sI[2][32];
    __shared__ int sCid[MM];
    int b = blockIdx.x;
    const float* X = xyz + b * NN * 3;
    int tid = threadIdx.x, lane = tid & 31, w = tid >> 5;

    unsigned long long pxp[2], pyp[2], pzp[2];
    float dd[4];
#pragma unroll
    for (int r2 = 0; r2 < 2; r2++) {
        int i0 = tid + ((2*r2) << 10), i1 = tid + ((2*r2+1) << 10);
        float x0 = X[3*i0], y0 = X[3*i0+1], z0 = X[3*i0+2];
        float x1 = X[3*i1], y1 = X[3*i1+1], z1 = X[3*i1+2];
        PACK_F32X2(pxp[r2], __float_as_uint(x0), __float_as_uint(x1));
        PACK_F32X2(pyp[r2], __float_as_uint(y0), __float_as_uint(y1));
        PACK_F32X2(pzp[r2], __float_as_uint(z0), __float_as_uint(z1));
        sP[i0] = make_float4(x0, y0, z0, 0.f);
        sP[i1] = make_float4(x1, y1, z1, 0.f);
        dd[2*r2] = 1e10f; dd[2*r2+1] = 1e10f;
    }
    __syncthreads();
    float lx = X[0], ly = X[1], lz = X[2];
    if (tid == 0) { d_cidx[b*MM] = 0; sCid[0] = 0; }

    for (int it = 1; it < MM; it++) {
        unsigned long long lx2, ly2, lz2;
        unsigned nx = __float_as_uint(-lx), ny = __float_as_uint(-ly), nz = __float_as_uint(-lz);
        PACK_F32X2(lx2, nx, nx);
        PACK_F32X2(ly2, ny, ny);
        PACK_F32X2(lz2, nz, nz);
#pragma unroll
        for (int r2 = 0; r2 < 2; r2++) {
            unsigned long long dx, dy, dz, s, t;
            ADD_F32X2(dx, pxp[r2], lx2);      // p - l (exact: x + (-lx))
            MUL_F32X2(s,  dx, dx);
            ADD_F32X2(dy, pyp[r2], ly2);
            MUL_F32X2(t,  dy, dy);
            ADD_F32X2(s,  s, t);
            ADD_F32X2(dz, pzp[r2], lz2);
            MUL_F32X2(t,  dz, dz);
            ADD_F32X2(s,  s, t);
            unsigned u0, u1; UNPACK_F32X2(u0, u1, s);
            dd[2*r2]   = fminf(dd[2*r2],   __uint_as_float(u0));
            dd[2*r2+1] = fminf(dd[2*r2+1], __uint_as_float(u1));
        }
        // per-thread argmax: max tree + first-match scan (lowest r = lowest idx)
        float bd = fmaxf(fmaxf(dd[0], dd[1]), fmaxf(dd[2], dd[3]));
        unsigned bi = (dd[0] == bd) ? (unsigned)tid
                    : (dd[1] == bd) ? (unsigned)(tid + 1024)
                    : (dd[2] == bd) ? (unsigned)(tid + 2048)
                    :                 (unsigned)(tid + 3072);
        unsigned d32 = __float_as_uint(bd);                     // nonneg floats order as uints
        unsigned wd  = __reduce_max_sync(0xffffffffu, d32);
        unsigned ic  = (d32 == wd) ? bi : 0xffffffffu;
        unsigned wi  = __reduce_min_sync(0xffffffffu, ic);
        int buf = it & 1;
        if (lane == 0) { sD[buf][w] = wd; sI[buf][w] = wi; }
        __syncthreads();
        unsigned td = sD[buf][lane];
        unsigned gd = __reduce_max_sync(0xffffffffu, td);
        unsigned ti = (td == gd) ? sI[buf][lane] : 0xffffffffu;
        unsigned gi = __reduce_min_sync(0xffffffffu, ti);
        if (tid == 0) d_cidx[b*MM + it] = (int)gi;
        if (tid == it) sCid[it] = (int)gi;
        float4 p = sP[gi];
        lx = p.x; ly = p.y; lz = p.z;
    }

    // fused gather: thread m emits new_xyz/new_comp (coords still in smem)
    __syncthreads();
    int m = tid;                         // 1024 threads == MM
    int ci = sCid[m];
    float4 p = sP[ci];
    int g = b*MM + m;
    d_nxyz[g*3+0] = p.x; d_nxyz[g*3+1] = p.y; d_nxyz[g*3+2] = p.z;
    out[g*3+0] = p.x; out[g*3+1] = p.y; out[g*3+2] = p.z;    // new_xyz
    int cp = comp[b*NN + ci];
    d_ncomp[g] = cp;
    out[BB*MM*3 + BB*256*MM + g] = (float)cp;                 // new_comp
}

// ================= feat1 = ReLU(features @ W1d^T + b) ========================
__global__ void __launch_bounds__(256) feat1_kernel(const float* __restrict__ F,
                                                    const float* __restrict__ W,
                                                    const float* __restrict__ bias) {
    __shared__ float sf[4][64];
    __shared__ float sw[64 * 65];
    int p0 = blockIdx.x << 2;
    int tid = threadIdx.x;
    for (int i = tid; i < 4096; i += 256) sw[(i >> 6) * 65 + (i & 63)] = W[i];
    { int p = tid >> 6, j = tid & 63; sf[p][j] = F[(p0 + p) * 64 + j]; }
    __syncthreads();
    int c = tid & 63, p = tid >> 6;
    float acc = bias[c];
#pragma unroll
    for (int j = 0; j < 64; j++) acc += sf[p][j] * sw[c * 65 + j];
    d_feat1[(p0 + p) * 64 + c] = fmaxf(acc, 0.f);
}

// ==== knn1: 32-NN among 4096 — winner-only rescan + REDUX (R8-proven) =======
__global__ void __launch_bounds__(256) knn1_kernel(const float* __restrict__ xyz) {
    int g = blockIdx.x, b = g >> 10;
    int tid = threadIdx.x, lane = tid & 31, w = tid >> 5;
    __shared__ unsigned sD[2][8], sI[2][8];
    const float* X = xyz + b * NN * 3;
    float qx = d_nxyz[g*3+0], qy = d_nxyz[g*3+1], qz = d_nxyz[g*3+2];

    unsigned long long k[16];
#pragma unroll
    for (int r = 0; r < 16; r++) {
        int i = tid + (r << 8);
        float d = sqdist(qx, qy, qz, X[3*i], X[3*i+1], X[3*i+2]);
        k[r] = ((unsigned long long)__float_as_uint(d) << 32) | (unsigned)(i + 1);  // keys > 0
    }
    unsigned long long cand = ~0ull;
#pragma unroll
    for (int r = 0; r < 16; r++)
        if (k[r] < cand) cand = k[r];

    for (int sel = 0; sel < KK1; sel++) {
        unsigned d32 = (unsigned)(cand >> 32);
        unsigned wd  = __reduce_min_sync(0xffffffffu, d32);
        unsigned ic  = (d32 == wd) ? (unsigned)cand : 0xffffffffu;
        unsigned wi  = __reduce_min_sync(0xffffffffu, ic);
        int buf = sel & 1;
        if (lane == 0) { sD[buf][w] = wd; sI[buf][w] = wi; }
        __syncthreads();
        unsigned td = (lane < 8) ? sD[buf][lane] : 0xffffffffu;
        unsigned bd = __reduce_min_sync(0xffffffffu, td);
        unsigned ti = (lane < 8 && td == bd) ? sI[buf][lane] : 0xffffffffu;
        unsigned bi = __reduce_min_sync(0xffffffffu, ti);
        if (tid == 0) d_idx1[g*KK1 + sel] = (int)bi - 1;
        unsigned long long winner = ((unsigned long long)bd << 32) | bi;
        if (cand == winner) {           // exactly one thread (keys unique)
            cand = ~0ull;
#pragma unroll
            for (int r = 0; r < 16; r++)
                if (k[r] > winner && k[r] < cand) cand = k[r];
        }
    }
}

// ==== knn2: comp-constrained 16-NN — winner-only rescan (R8-proven, 15us) ===
__global__ void __launch_bounds__(256) knn2_kernel() {
    int g = blockIdx.x, b = g >> 10;
    int tid = threadIdx.x, lane = tid & 31, w = tid >> 5;
    __shared__ unsigned sD[2][8], sI[2][8];
    const float* RX = d_nxyz + b * MM * 3;
    const int* RC = d_ncomp + b * MM;
    float qx = d_nxyz[g*3+0], qy = d_nxyz[g*3+1], qz = d_nxyz[g*3+2];
    int qc = d_ncomp[g];

    unsigned long long k[4];
#pragma unroll
    for (int r = 0; r < 4; r++) {
        int i = tid + (r << 8);
        float d = sqdist(qx, qy, qz, RX[3*i], RX[3*i+1], RX[3*i+2]);
        if (RC[i] != qc) d = __fadd_rn(d, 1e9f);
        k[r] = ((unsigned long long)__float_as_uint(d) << 32) | (unsigned)(i + 1);  // keys > 0
    }
    unsigned long long cand = ~0ull;
#pragma unroll
    for (int r = 0; r < 4; r++)
        if (k[r] < cand) cand = k[r];

    for (int sel = 0; sel < KK2; sel++) {
        unsigned d32 = (unsigned)(cand >> 32);
        unsigned wd  = __reduce_min_sync(0xffffffffu, d32);
        unsigned ic  = (d32 == wd) ? (unsigned)cand : 0xffffffffu;
        unsigned wi  = __reduce_min_sync(0xffffffffu, ic);
        int buf = sel & 1;
        if (lane == 0) { sD[buf][w] = wd; sI[buf][w] = wi; }
        __syncthreads();
        unsigned td = (lane < 8) ? sD[buf][lane] : 0xffffffffu;
        unsigned bd = __reduce_min_sync(0xffffffffu, td);
        unsigned ti = (lane < 8 && td == bd) ? sI[buf][lane] : 0xffffffffu;
        unsigned bi = __reduce_min_sync(0xffffffffu, ti);
        if (tid == 0) d_idx2[g*KK2 + sel] = (int)bi - 1;
        unsigned long long winner = ((unsigned long long)bd << 32) | bi;
        if (cand == winner) {
            cand = ~0ull;
#pragma unroll
            for (int r = 0; r < 4; r++)
                if (k[r] > winner && k[r] < cand) cand = k[r];
        }
    }
}

// ===== stage 1: weights [j][o] stride 97; s_w padded to 16B multiple ========
__global__ void __launch_bounds__(96) stage1_kernel(
    const float* __restrict__ xyz,
    const float* __restrict__ Wdx1, const float* __restrict__ bdx1,
    const float* __restrict__ Ww1,  const float* __restrict__ bw1) {
    int g = blockIdx.x, b = g >> 10, tid = threadIdx.x;
    __shared__ float s_w[6500];                      // 67*97=6499, +1 pad -> 26000 B (16B mult)
    __shared__ __align__(16) float s_in[67*36];      // [j][k], float4-read rows
    __shared__ float s_c[64];
    __shared__ int s_idx[KK1];
    __shared__ float s_q[3];

    for (int e = tid; e < 96*67; e += 96) { int o = e/67, j = e - o*67; s_w[j*97+o] = Ww1[e]; }
    if (tid < KK1) s_idx[tid] = d_idx1[g*KK1 + tid];
    if (tid < 3)   s_q[tid] = d_nxyz[g*3 + tid];
    if (tid >= 32 && tid < 96) {
        int c = tid - 32;
        float cv = d_feat1[(b*NN + d_cidx[g]) * 64 + c];
        s_c[c] = cv;
        d_center[g*64 + c] = cv;
    }
    __syncthreads();
    for (int e = tid; e < 2048; e += 96) {
        int k = e >> 6, c = e & 63;
        s_in[(3+c)*36 + k] = d_feat1[(b*NN + s_idx[k]) * 64 + c] - s_c[c];
    }
    if (tid < KK1) {
        int gi = s_idx[tid];
        s_in[0*36 + tid] = xyz[(b*NN+gi)*3+0] - s_q[0];
        s_in[1*36 + tid] = xyz[(b*NN+gi)*3+1] - s_q[1];
        s_in[2*36 + tid] = xyz[(b*NN+gi)*3+2] - s_q[2];
    }
    __syncthreads();

    int o = tid;
    float a[KK1];
    float bv = bw1[o];
#pragma unroll
    for (int k = 0; k < KK1; k++) a[k] = bv;
    for (int j = 0; j < 67; j++) {
        float wv = s_w[j*97 + o];
        const float4* row = (const float4*)&s_in[j*36];
#pragma unroll
        for (int q = 0; q < 8; q++) {
            float4 v = row[q];
            a[4*q+0] += v.x*wv; a[4*q+1] += v.y*wv;
            a[4*q+2] += v.z*wv; a[4*q+3] += v.w*wv;
        }
    }
    float mx = 0.f;
#pragma unroll
    for (int k = 0; k < KK1; k++) { a[k] = fmaxf(a[k], 0.f); mx = fmaxf(mx, a[k]); }
    d_cfea1[g*96 + o] = mx;
    float se = 0.f;
#pragma unroll
    for (int k = 0; k < KK1; k++) { a[k] = __expf(a[k] - mx); se += a[k]; }
    float res = 0.f;
    if (o < 32) {
        float w0 = Wdx1[o*3], w1 = Wdx1[o*3+1], w2 = Wdx1[o*3+2], bb = bdx1[o];
#pragma unroll
        for (int k = 0; k < KK1; k++) {
            float val = fmaxf(s_in[k]*w0 + s_in[36+k]*w1 + s_in[72+k]*w2 + bb, 0.f);
            res += val * a[k];
        }
    } else {
        int c = o - 32;
#pragma unroll
        for (int k = 0; k < KK1; k++) res += (s_in[(3+c)*36 + k] + s_c[c]) * a[k];
    }
    d_gfea1[g*96 + o] = __fdividef(res, se);
}

// ===== stage 2: weights [j][o] stride 129, region padded for alignment ======
#define S2W 12772   // 99*129 = 12771, padded: 51088 B, 16B multiple
__global__ void __launch_bounds__(128) stage2_kernel(
    const float* __restrict__ Wdx2, const float* __restrict__ bdx2,
    const float* __restrict__ Ww2,  const float* __restrict__ bw2) {
    int g = blockIdx.x, b = g >> 10, tid = threadIdx.x;
    extern __shared__ float sm2[];
    float* s_w  = sm2;            // [99][129]
    float* s_in = sm2 + S2W;      // [99][20], 16B-aligned
    __shared__ float s_c[96];
    __shared__ int s_idx[KK2];
    __shared__ float s_q[3];

    for (int e = tid; e < 128*99; e += 128) { int o = e/99, j = e - o*99; s_w[j*129+o] = Ww2[e]; }
    if (tid < KK2) s_idx[tid] = d_idx2[g*KK2 + tid];
    if (tid < 3)   s_q[tid] = d_nxyz[g*3 + tid];
    if (tid < 96)  s_c[tid] = d_gfea1[g*96 + tid];
    __syncthreads();
    for (int e = tid; e < KK2*96; e += 128) {
        int k = e / 96, c = e - k*96;
        s_in[c*20 + k] = d_gfea1[((b<<10) + s_idx[k]) * 96 + c] - s_c[c];
    }
    if (tid < KK2) {
        int gi = (b<<10) + s_idx[tid];
        s_in[96*20 + tid] = d_nxyz[gi*3+0] - s_q[0];
        s_in[97*20 + tid] = d_nxyz[gi*3+1] - s_q[1];
        s_in[98*20 + tid] = d_nxyz[gi*3+2] - s_q[2];
    }
    __syncthreads();

    int o = tid;
    float a[KK2];
    float bv = bw2[o];
#pragma unroll
    for (int k = 0; k < KK2; k++) a[k] = bv;
    for (int j = 0; j < 99; j++) {
        float wv = s_w[j*129 + o];
        const float4* row = (const float4*)&s_in[j*20];
#pragma unroll
        for (int q = 0; q < 4; q++) {
            float4 v = row[q];
            a[4*q+0] += v.x*wv; a[4*q+1] += v.y*wv;
            a[4*q+2] += v.z*wv; a[4*q+3] += v.w*wv;
        }
    }
    float mx = 0.f;
#pragma unroll
    for (int k = 0; k < KK2; k++) { a[k] = fmaxf(a[k], 0.f); mx = fmaxf(mx, a[k]); }
    d_cfea2[g*128 + o] = mx;
    float se = 0.f;
#pragma unroll
    for (int k = 0; k < KK2; k++) { a[k] = __expf(a[k] - mx); se += a[k]; }
    float res = 0.f;
    if (o < 32) {
        float w0 = Wdx2[o*3], w1 = Wdx2[o*3+1], w2 = Wdx2[o*3+2], bb = bdx2[o];
#pragma unroll
        for (int k = 0; k < KK2; k++) {
            float val = fmaxf(s_in[96*20+k]*w0 + s_in[97*20+k]*w1 + s_in[98*20+k]*w2 + bb, 0.f);
            res += val * a[k];
        }
    } else {
        int c = o - 32;
#pragma unroll
        for (int k = 0; k < KK2; k++) res += (s_in[c*20 + k] + s_c[c]) * a[k];
    }
    d_gfea2[g*128 + o] = __fdividef(res, se);
}

// ===== stage 3b: weights [j][o] stride 129; max-pool only (idx3 == idx2) ====
#define S3W 16900   // 131*129 = 16899, padded: 67600 B, 16B multiple
__global__ void __launch_bounds__(128) stage3b_kernel(
    const float* __restrict__ Wsp3, const float* __restrict__ bsp3) {
    int g = blockIdx.x, b = g >> 10, tid = threadIdx.x;
    extern __shared__ float sm3[];
    float* s_w  = sm3;                // [131][129]
    float* s_in = sm3 + S3W;          // [131][20], 16B-aligned
    __shared__ float s_c[128];
    __shared__ int s_idx[KK2];
    __shared__ float s_q[3];

    for (int e = tid; e < 128*131; e += 128) { int o = e/131, j = e - o*131; s_w[j*129+o] = Wsp3[e]; }
    if (tid < KK2) s_idx[tid] = d_idx2[g*KK2 + tid];
    if (tid < 3)   s_q[tid] = d_nxyz[g*3 + tid];
    s_c[tid] = d_gfea2[g*128 + tid];
    __syncthreads();
    for (int e = tid; e < KK2*128; e += 128) {
        int k = e >> 7, c = e & 127;
        s_in[c*20 + k] = d_gfea2[((b<<10) + s_idx[k]) * 128 + c] - s_c[c];
    }
    if (tid < KK2) {
        int gi = (b<<10) + s_idx[tid];
        s_in[128*20 + tid] = d_nxyz[gi*3+0] - s_q[0];
        s_in[129*20 + tid] = d_nxyz[gi*3+1] - s_q[1];
        s_in[130*20 + tid] = d_nxyz[gi*3+2] - s_q[2];
    }
    __syncthreads();

    int o = tid;
    float a[KK2];
    float bv = bsp3[o];
#pragma unroll
    for (int k = 0; k < KK2; k++) a[k] = bv;
    for (int j = 0; j < 131; j++) {
        float wv = s_w[j*129 + o];
        const float4* row = (const float4*)&s_in[j*20];
#pragma unroll
        for (int q = 0; q < 4; q++) {
            float4 v = row[q];
            a[4*q+0] += v.x*wv; a[4*q+1] += v.y*wv;
            a[4*q+2] += v.z*wv; a[4*q+3] += v.w*wv;
        }
    }
    float mx = 0.f;
#pragma unroll
    for (int k = 0; k < KK2; k++) mx = fmaxf(mx, fmaxf(a[k], 0.f));
    d_lpf[g*128 + o] = mx;
}

// ================= final: ReLU(concat(768) @ Wnew^T + bnew) -> (B,256,M) =====
__global__ void __launch_bounds__(256) final_kernel(const float* __restrict__ Wnew,
                                                    const float* __restrict__ bnew,
                                                    float* __restrict__ out) {
    int g0 = blockIdx.x * 8;
    int tid = threadIdx.x;
    __shared__ float XT[768*8];   // [j][p]
    for (int e = tid; e < 8*128; e += 256) {
        int p = e >> 7, c = e & 127, g = g0 + p;
        float v = d_cfea2[g*128 + c];
        XT[c*8 + p] = v;                    // g_fea3 == c_fea2
        XT[(384+c)*8 + p] = v;              // c_fea2
        XT[(128+c)*8 + p] = d_lpf[g*128 + c];
        XT[(256+c)*8 + p] = d_gfea2[g*128 + c];
    }
    for (int e = tid; e < 8*96; e += 256) {
        int p = e / 96, c = e - p*96, g = g0 + p;
        XT[(512+c)*8 + p] = d_gfea1[g*96 + c];
        XT[(608+c)*8 + p] = d_cfea1[g*96 + c];
    }
    for (int e = tid; e < 8*64; e += 256) {
        int p = e >> 6, c = e & 63, g = g0 + p;
        XT[(704+c)*8 + p] = d_center[g*64 + c];
    }
    __syncthreads();

    int o = tid;
    float acc[8];
    float bv = bnew[o];
#pragma unroll
    for (int p = 0; p < 8; p++) acc[p] = bv;
    const float* wr = Wnew + o*768;
#pragma unroll 4
    for (int j = 0; j < 768; j++) {
        float wv = __ldg(wr + j);
        float4 v0 = *(const float4*)&XT[j*8];
        float4 v1 = *(const float4*)&XT[j*8 + 4];
        acc[0] += v0.x*wv; acc[1] += v0.y*wv; acc[2] += v0.z*wv; acc[3] += v0.w*wv;
        acc[4] += v1.x*wv; acc[5] += v1.y*wv; acc[6] += v1.z*wv; acc[7] += v1.w*wv;
    }
#pragma unroll
    for (int p = 0; p < 8; p++) {
        int g = g0 + p, b = g >> 10, m = g & 1023;
        out[BB*MM*3 + b*256*MM + o*MM + m] = fmaxf(acc[p], 0.f);
    }
}

extern "C" void kernel_launch(void* const* d_in, const int* in_sizes, int n_in,
                              void* d_out, int out_size) {
    const float* xyz      = (const float*)d_in[0];
    const float* features = (const float*)d_in[1];
    const int*   comp     = (const int*)d_in[2];
    const float* W1d  = (const float*)d_in[3];
    const float* b1d  = (const float*)d_in[4];
    const float* Wdx1 = (const float*)d_in[5];
    const float* bdx1 = (const float*)d_in[6];
    const float* Ww1  = (const float*)d_in[7];
    const float* bw1  = (const float*)d_in[8];
    const float* Wdx2 = (const float*)d_in[9];
    const float* bdx2 = (const float*)d_in[10];
    const float* Ww2  = (const float*)d_in[11];
    const float* bw2  = (const float*)d_in[12];
    // d_in[13], d_in[14] = Ww3, bw3 — unused (stage-3 attention is the identity)
    const float* Wsp3 = (const float*)d_in[15];
    const float* bsp3 = (const float*)d_in[16];
    const float* Wnew = (const float*)d_in[17];
    const float* bnew = (const float*)d_in[18];
    float* out = (float*)d_out;

    static const int SMF = NN * 16;                      // 65536 B (fps coords)
    static const int SM2 = (S2W + 99*20) * 4;            // 59008 B
    static const int SM3 = (S3W + 131*20) * 4;           // 78080 B
    cudaFuncSetAttribute(fps_kernel,     cudaFuncAttributeMaxDynamicSharedMemorySize, SMF);
    cudaFuncSetAttribute(stage2_kernel,  cudaFuncAttributeMaxDynamicSharedMemorySize, SM2);
    cudaFuncSetAttribute(stage3b_kernel, cudaFuncAttributeMaxDynamicSharedMemorySize, SM3);

    // dependency-legal order with stage1 in profile slot 4
    fps_kernel<<<BB, 1024, SMF>>>(xyz, comp, out);        // includes fused gather
    knn1_kernel<<<BB*MM, 256>>>(xyz);
    feat1_kernel<<<BB*NN/4, 256>>>(features, W1d, b1d);
    stage1_kernel<<<BB*MM, 96>>>(xyz, Wdx1, bdx1, Ww1, bw1);   // profiled this round
    knn2_kernel<<<BB*MM, 256>>>();
    stage2_kernel<<<BB*MM, 128, SM2>>>(Wdx2, bdx2, Ww2, bw2);
    stage3b_kernel<<<BB*MM, 128, SM3>>>(Wsp3, bsp3);
    final_kernel<<<BB*MM/8, 256>>>(Wnew, bnew, out);
}

// round 16
// speedup vs baseline: 1.2413x; 1.1052x over previous
#include <cuda_runtime.h>

#define BB 2
#define NN 4096
#define MM 1024
#define KK1 32
#define KK2 16

// packed f32x2 helpers (sm_103a) — PTX forms from ptx_helpers.cuh (R9/R13-validated)
#define MUL_F32X2(out, a, b) asm("mul.rn.f32x2 %0, %1, %2;" : "=l"(out) : "l"(a), "l"(b))
#define ADD_F32X2(out, a, b) asm("add.rn.f32x2 %0, %1, %2;" : "=l"(out) : "l"(a), "l"(b))
#define PACK_F32X2(out, lo, hi) asm("mov.b64 %0, {%1, %2};" : "=l"(out) : "r"(lo), "r"(hi))
#define UNPACK_F32X2(lo, hi, in) asm("mov.b64 {%0, %1}, %2;" : "=r"(lo), "=r"(hi) : "l"(in))

// ---- scratch (device globals; no allocations allowed) ----
__device__ int   d_cidx[BB*MM];
__device__ float d_nxyz[BB*MM*3];
__device__ int   d_ncomp[BB*MM];
__device__ float d_feat1[BB*NN*64];
__device__ int   d_idx1[BB*MM*KK1];
__device__ int   d_idx2[BB*MM*KK2];
__device__ float d_center[BB*MM*64];
__device__ float d_cfea1[BB*MM*96];
__device__ float d_gfea1[BB*MM*96];
__device__ float d_cfea2[BB*MM*128];
__device__ float d_gfea2[BB*MM*128];
__device__ float d_lpf[BB*MM*128];
// transposed weights [j][o], filled once per launch by prep_kernel
__device__ float d_w1T[67*96];
__device__ float d_w2T[99*128];
__device__ float d_w3T[131*128];

__device__ __forceinline__ float sqdist(float ax, float ay, float az,
                                        float bx, float by, float bz) {
    // bit-exact vs reference: no FMA contraction, (dx^2+dy^2)+dz^2 order
    float dx = __fsub_rn(ax, bx), dy = __fsub_rn(ay, by), dz = __fsub_rn(az, bz);
    return __fadd_rn(__fadd_rn(__fmul_rn(dx, dx), __fmul_rn(dy, dy)), __fmul_rn(dz, dz));
}

// ======= prep: transpose stage weights once ([o][j] -> [j][o]) ==============
__global__ void prep_kernel(const float* __restrict__ Ww1,
                            const float* __restrict__ Ww2,
                            const float* __restrict__ Wsp3) {
    int i = blockIdx.x * 256 + threadIdx.x;
    if (i < 96*67)  { int o = i/67,  j = i - o*67;  d_w1T[j*96  + o] = Ww1[i]; }
    if (i < 128*99) { int o = i/99,  j = i - o*99;  d_w2T[j*128 + o] = Ww2[i]; }
    if (i < 128*131){ int o = i/131, j = i - o*131; d_w3T[j*128 + o] = Wsp3[i]; }
}

// ======== FPS (+fused gather): 1024 thr, 4 pts/thr, f32x2 + REDUX argmax ====
// R13-proven: 347us, bit-exact.
__global__ void __launch_bounds__(1024) fps_kernel(const float* __restrict__ xyz,
                                                   const int* __restrict__ comp,
                                                   float* __restrict__ out) {
    extern __shared__ float4 sP[];               // 4096 points, 64KB
    __shared__ unsigned sD[2][32], sI[2][32];
    __shared__ int sCid[MM];
    int b = blockIdx.x;
    const float* X = xyz + b * NN * 3;
    int tid = threadIdx.x, lane = tid & 31, w = tid >> 5;

    unsigned long long pxp[2], pyp[2], pzp[2];
    float dd[4];
#pragma unroll
    for (int r2 = 0; r2 < 2; r2++) {
        int i0 = tid + ((2*r2) << 10), i1 = tid + ((2*r2+1) << 10);
        float x0 = X[3*i0], y0 = X[3*i0+1], z0 = X[3*i0+2];
        float x1 = X[3*i1], y1 = X[3*i1+1], z1 = X[3*i1+2];
        PACK_F32X2(pxp[r2], __float_as_uint(x0), __float_as_uint(x1));
        PACK_F32X2(pyp[r2], __float_as_uint(y0), __float_as_uint(y1));
        PACK_F32X2(pzp[r2], __float_as_uint(z0), __float_as_uint(z1));
        sP[i0] = make_float4(x0, y0, z0, 0.f);
        sP[i1] = make_float4(x1, y1, z1, 0.f);
        dd[2*r2] = 1e10f; dd[2*r2+1] = 1e10f;
    }
    __syncthreads();
    float lx = X[0], ly = X[1], lz = X[2];
    if (tid == 0) { d_cidx[b*MM] = 0; sCid[0] = 0; }

    for (int it = 1; it < MM; it++) {
        unsigned long long lx2, ly2, lz2;
        unsigned nx = __float_as_uint(-lx), ny = __float_as_uint(-ly), nz = __float_as_uint(-lz);
        PACK_F32X2(lx2, nx, nx);
        PACK_F32X2(ly2, ny, ny);
        PACK_F32X2(lz2, nz, nz);
#pragma unroll
        for (int r2 = 0; r2 < 2; r2++) {
            unsigned long long dx, dy, dz, s, t;
            ADD_F32X2(dx, pxp[r2], lx2);      // p - l (exact: x + (-lx))
            MUL_F32X2(s,  dx, dx);
            ADD_F32X2(dy, pyp[r2], ly2);
            MUL_F32X2(t,  dy, dy);
            ADD_F32X2(s,  s, t);
            ADD_F32X2(dz, pzp[r2], lz2);
            MUL_F32X2(t,  dz, dz);
            ADD_F32X2(s,  s, t);
            unsigned u0, u1; UNPACK_F32X2(u0, u1, s);
            dd[2*r2]   = fminf(dd[2*r2],   __uint_as_float(u0));
            dd[2*r2+1] = fminf(dd[2*r2+1], __uint_as_float(u1));
        }
        float bd = fmaxf(fmaxf(dd[0], dd[1]), fmaxf(dd[2], dd[3]));
        unsigned bi = (dd[0] == bd) ? (unsigned)tid
                    : (dd[1] == bd) ? (unsigned)(tid + 1024)
                    : (dd[2] == bd) ? (unsigned)(tid + 2048)
                    :                 (unsigned)(tid + 3072);
        unsigned d32 = __float_as_uint(bd);
        unsigned wd  = __reduce_max_sync(0xffffffffu, d32);
        unsigned ic  = (d32 == wd) ? bi : 0xffffffffu;
        unsigned wi  = __reduce_min_sync(0xffffffffu, ic);
        int buf = it & 1;
        if (lane == 0) { sD[buf][w] = wd; sI[buf][w] = wi; }
        __syncthreads();
        unsigned td = sD[buf][lane];
        unsigned gd = __reduce_max_sync(0xffffffffu, td);
        unsigned ti = (td == gd) ? sI[buf][lane] : 0xffffffffu;
        unsigned gi = __reduce_min_sync(0xffffffffu, ti);
        if (tid == 0) d_cidx[b*MM + it] = (int)gi;
        if (tid == it) sCid[it] = (int)gi;
        float4 p = sP[gi];
        lx = p.x; ly = p.y; lz = p.z;
    }

    // fused gather
    __syncthreads();
    int m = tid;
    int ci = sCid[m];
    float4 p = sP[ci];
    int g = b*MM + m;
    d_nxyz[g*3+0] = p.x; d_nxyz[g*3+1] = p.y; d_nxyz[g*3+2] = p.z;
    out[g*3+0] = p.x; out[g*3+1] = p.y; out[g*3+2] = p.z;    // new_xyz
    int cp = comp[b*NN + ci];
    d_ncomp[g] = cp;
    out[BB*MM*3 + BB*256*MM + g] = (float)cp;                 // new_comp
}

// ================= feat1 = ReLU(features @ W1d^T + b) ========================
__global__ void __launch_bounds__(256) feat1_kernel(const float* __restrict__ F,
                                                    const float* __restrict__ W,
                                                    const float* __restrict__ bias) {
    __shared__ float sf[4][64];
    __shared__ float sw[64 * 65];
    int p0 = blockIdx.x << 2;
    int tid = threadIdx.x;
    for (int i = tid; i < 4096; i += 256) sw[(i >> 6) * 65 + (i & 63)] = W[i];
    { int p = tid >> 6, j = tid & 63; sf[p][j] = F[(p0 + p) * 64 + j]; }
    __syncthreads();
    int c = tid & 63, p = tid >> 6;
    float acc = bias[c];
#pragma unroll
    for (int j = 0; j < 64; j++) acc += sf[p][j] * sw[c * 65 + j];
    d_feat1[(p0 + p) * 64 + c] = fmaxf(acc, 0.f);
}

// ==== knn1: 32-NN among 4096 — winner-only rescan + REDUX (R8-proven) =======
__global__ void __launch_bounds__(256) knn1_kernel(const float* __restrict__ xyz) {
    int g = blockIdx.x, b = g >> 10;
    int tid = threadIdx.x, lane = tid & 31, w = tid >> 5;
    __shared__ unsigned sD[2][8], sI[2][8];
    const float* X = xyz + b * NN * 3;
    float qx = d_nxyz[g*3+0], qy = d_nxyz[g*3+1], qz = d_nxyz[g*3+2];

    unsigned long long k[16];
#pragma unroll
    for (int r = 0; r < 16; r++) {
        int i = tid + (r << 8);
        float d = sqdist(qx, qy, qz, X[3*i], X[3*i+1], X[3*i+2]);
        k[r] = ((unsigned long long)__float_as_uint(d) << 32) | (unsigned)(i + 1);  // keys > 0
    }
    unsigned long long cand = ~0ull;
#pragma unroll
    for (int r = 0; r < 16; r++)
        if (k[r] < cand) cand = k[r];

    for (int sel = 0; sel < KK1; sel++) {
        unsigned d32 = (unsigned)(cand >> 32);
        unsigned wd  = __reduce_min_sync(0xffffffffu, d32);
        unsigned ic  = (d32 == wd) ? (unsigned)cand : 0xffffffffu;
        unsigned wi  = __reduce_min_sync(0xffffffffu, ic);
        int buf = sel & 1;
        if (lane == 0) { sD[buf][w] = wd; sI[buf][w] = wi; }
        __syncthreads();
        unsigned td = (lane < 8) ? sD[buf][lane] : 0xffffffffu;
        unsigned bd = __reduce_min_sync(0xffffffffu, td);
        unsigned ti = (lane < 8 && td == bd) ? sI[buf][lane] : 0xffffffffu;
        unsigned bi = __reduce_min_sync(0xffffffffu, ti);
        if (tid == 0) d_idx1[g*KK1 + sel] = (int)bi - 1;
        unsigned long long winner = ((unsigned long long)bd << 32) | bi;
        if (cand == winner) {
            cand = ~0ull;
#pragma unroll
            for (int r = 0; r < 16; r++)
                if (k[r] > winner && k[r] < cand) cand = k[r];
        }
    }
}

// ==== knn2: comp-constrained 16-NN — winner-only rescan (R8-proven, 15us) ===
__global__ void __launch_bounds__(256) knn2_kernel() {
    int g = blockIdx.x, b = g >> 10;
    int tid = threadIdx.x, lane = tid & 31, w = tid >> 5;
    __shared__ unsigned sD[2][8], sI[2][8];
    const float* RX = d_nxyz + b * MM * 3;
    const int* RC = d_ncomp + b * MM;
    float qx = d_nxyz[g*3+0], qy = d_nxyz[g*3+1], qz = d_nxyz[g*3+2];
    int qc = d_ncomp[g];

    unsigned long long k[4];
#pragma unroll
    for (int r = 0; r < 4; r++) {
        int i = tid + (r << 8);
        float d = sqdist(qx, qy, qz, RX[3*i], RX[3*i+1], RX[3*i+2]);
        if (RC[i] != qc) d = __fadd_rn(d, 1e9f);
        k[r] = ((unsigned long long)__float_as_uint(d) << 32) | (unsigned)(i + 1);  // keys > 0
    }
    unsigned long long cand = ~0ull;
#pragma unroll
    for (int r = 0; r < 4; r++)
        if (k[r] < cand) cand = k[r];

    for (int sel = 0; sel < KK2; sel++) {
        unsigned d32 = (unsigned)(cand >> 32);
        unsigned wd  = __reduce_min_sync(0xffffffffu, d32);
        unsigned ic  = (d32 == wd) ? (unsigned)cand : 0xffffffffu;
        unsigned wi  = __reduce_min_sync(0xffffffffu, ic);
        int buf = sel & 1;
        if (lane == 0) { sD[buf][w] = wd; sI[buf][w] = wi; }
        __syncthreads();
        unsigned td = (lane < 8) ? sD[buf][lane] : 0xffffffffu;
        unsigned bd = __reduce_min_sync(0xffffffffu, td);
        unsigned ti = (lane < 8 && td == bd) ? sI[buf][lane] : 0xffffffffu;
        unsigned bi = __reduce_min_sync(0xffffffffu, ti);
        if (tid == 0) d_idx2[g*KK2 + sel] = (int)bi - 1;
        unsigned long long winner = ((unsigned long long)bd << 32) | bi;
        if (cand == winner) {
            cand = ~0ull;
#pragma unroll
            for (int r = 0; r < 4; r++)
                if (k[r] > winner && k[r] < cand) cand = k[r];
        }
    }
}

// ===== stage 1: weights via __ldg from pre-transposed d_w1T ([j][o]) ========
__global__ void __launch_bounds__(96) stage1_kernel(
    const float* __restrict__ xyz,
    const float* __restrict__ Wdx1, const float* __restrict__ bdx1,
    const float* __restrict__ bw1) {
    int g = blockIdx.x, b = g >> 10, tid = threadIdx.x;
    __shared__ __align__(16) float s_in[67*36];      // [j][k], float4-read rows
    __shared__ float s_c[64];
    __shared__ int s_idx[KK1];
    __shared__ float s_q[3];

    if (tid < KK1) s_idx[tid] = d_idx1[g*KK1 + tid];
    if (tid < 3)   s_q[tid] = d_nxyz[g*3 + tid];
    if (tid >= 32 && tid < 96) {
        int c = tid - 32;
        float cv = d_feat1[(b*NN + d_cidx[g]) * 64 + c];
        s_c[c] = cv;
        d_center[g*64 + c] = cv;
    }
    __syncthreads();
    for (int e = tid; e < 2048; e += 96) {
        int k = e >> 6, c = e & 63;
        s_in[(3+c)*36 + k] = d_feat1[(b*NN + s_idx[k]) * 64 + c] - s_c[c];
    }
    if (tid < KK1) {
        int gi = s_idx[tid];
        s_in[0*36 + tid] = xyz[(b*NN+gi)*3+0] - s_q[0];
        s_in[1*36 + tid] = xyz[(b*NN+gi)*3+1] - s_q[1];
        s_in[2*36 + tid] = xyz[(b*NN+gi)*3+2] - s_q[2];
    }
    __syncthreads();

    int o = tid;
    float a[KK1];
    float bv = bw1[o];
#pragma unroll
    for (int k = 0; k < KK1; k++) a[k] = bv;
    for (int j = 0; j < 67; j++) {
        float wv = __ldg(&d_w1T[j*96 + o]);
        const float4* row = (const float4*)&s_in[j*36];
#pragma unroll
        for (int q = 0; q < 8; q++) {
            float4 v = row[q];
            a[4*q+0] += v.x*wv; a[4*q+1] += v.y*wv;
            a[4*q+2] += v.z*wv; a[4*q+3] += v.w*wv;
        }
    }
    float mx = 0.f;
#pragma unroll
    for (int k = 0; k < KK1; k++) { a[k] = fmaxf(a[k], 0.f); mx = fmaxf(mx, a[k]); }
    d_cfea1[g*96 + o] = mx;
    float se = 0.f;
#pragma unroll
    for (int k = 0; k < KK1; k++) { a[k] = __expf(a[k] - mx); se += a[k]; }
    float res = 0.f;
    if (o < 32) {
        float w0 = Wdx1[o*3], w1 = Wdx1[o*3+1], w2 = Wdx1[o*3+2], bb = bdx1[o];
#pragma unroll
        for (int k = 0; k < KK1; k++) {
            float val = fmaxf(s_in[k]*w0 + s_in[36+k]*w1 + s_in[72+k]*w2 + bb, 0.f);
            res += val * a[k];
        }
    } else {
        int c = o - 32;
#pragma unroll
        for (int k = 0; k < KK1; k++) res += (s_in[(3+c)*36 + k] + s_c[c]) * a[k];
    }
    d_gfea1[g*96 + o] = __fdividef(res, se);
}

// ===== stage 2: weights via __ldg from pre-transposed d_w2T ([j][o]) ========
__global__ void __launch_bounds__(128) stage2_kernel(
    const float* __restrict__ Wdx2, const float* __restrict__ bdx2,
    const float* __restrict__ bw2) {
    int g = blockIdx.x, b = g >> 10, tid = threadIdx.x;
    __shared__ __align__(16) float s_in[99*20];
    __shared__ float s_c[96];
    __shared__ int s_idx[KK2];
    __shared__ float s_q[3];

    if (tid < KK2) s_idx[tid] = d_idx2[g*KK2 + tid];
    if (tid < 3)   s_q[tid] = d_nxyz[g*3 + tid];
    if (tid < 96)  s_c[tid] = d_gfea1[g*96 + tid];
    __syncthreads();
    for (int e = tid; e < KK2*96; e += 128) {
        int k = e / 96, c = e - k*96;
        s_in[c*20 + k] = d_gfea1[((b<<10) + s_idx[k]) * 96 + c] - s_c[c];
    }
    if (tid < KK2) {
        int gi = (b<<10) + s_idx[tid];
        s_in[96*20 + tid] = d_nxyz[gi*3+0] - s_q[0];
        s_in[97*20 + tid] = d_nxyz[gi*3+1] - s_q[1];
        s_in[98*20 + tid] = d_nxyz[gi*3+2] - s_q[2];
    }
    __syncthreads();

    int o = tid;
    float a[KK2];
    float bv = bw2[o];
#pragma unroll
    for (int k = 0; k < KK2; k++) a[k] = bv;
    for (int j = 0; j < 99; j++) {
        float wv = __ldg(&d_w2T[j*128 + o]);
        const float4* row = (const float4*)&s_in[j*20];
#pragma unroll
        for (int q = 0; q < 4; q++) {
            float4 v = row[q];
            a[4*q+0] += v.x*wv; a[4*q+1] += v.y*wv;
            a[4*q+2] += v.z*wv; a[4*q+3] += v.w*wv;
        }
    }
    float mx = 0.f;
#pragma unroll
    for (int k = 0; k < KK2; k++) { a[k] = fmaxf(a[k], 0.f); mx = fmaxf(mx, a[k]); }
    d_cfea2[g*128 + o] = mx;
    float se = 0.f;
#pragma unroll
    for (int k = 0; k < KK2; k++) { a[k] = __expf(a[k] - mx); se += a[k]; }
    float res = 0.f;
    if (o < 32) {
        float w0 = Wdx2[o*3], w1 = Wdx2[o*3+1], w2 = Wdx2[o*3+2], bb = bdx2[o];
#pragma unroll
        for (int k = 0; k < KK2; k++) {
            float val = fmaxf(s_in[96*20+k]*w0 + s_in[97*20+k]*w1 + s_in[98*20+k]*w2 + bb, 0.f);
            res += val * a[k];
        }
    } else {
        int c = o - 32;
#pragma unroll
        for (int k = 0; k < KK2; k++) res += (s_in[c*20 + k] + s_c[c]) * a[k];
    }
    d_gfea2[g*128 + o] = __fdividef(res, se);
}

// ===== stage 3b: weights via __ldg from pre-transposed d_w3T ([j][o]) =======
__global__ void __launch_bounds__(128) stage3b_kernel(
    const float* __restrict__ bsp3) {
    int g = blockIdx.x, b = g >> 10, tid = threadIdx.x;
    __shared__ __align__(16) float s_in[131*20];
    __shared__ float s_c[128];
    __shared__ int s_idx[KK2];
    __shared__ float s_q[3];

    if (tid < KK2) s_idx[tid] = d_idx2[g*KK2 + tid];
    if (tid < 3)   s_q[tid] = d_nxyz[g*3 + tid];
    s_c[tid] = d_gfea2[g*128 + tid];
    __syncthreads();
    for (int e = tid; e < KK2*128; e += 128) {
        int k = e >> 7, c = e & 127;
        s_in[c*20 + k] = d_gfea2[((b<<10) + s_idx[k]) * 128 + c] - s_c[c];
    }
    if (tid < KK2) {
        int gi = (b<<10) + s_idx[tid];
        s_in[128*20 + tid] = d_nxyz[gi*3+0] - s_q[0];
        s_in[129*20 + tid] = d_nxyz[gi*3+1] - s_q[1];
        s_in[130*20 + tid] = d_nxyz[gi*3+2] - s_q[2];
    }
    __syncthreads();

    int o = tid;
    float a[KK2];
    float bv = bsp3[o];
#pragma unroll
    for (int k = 0; k < KK2; k++) a[k] = bv;
    for (int j = 0; j < 131; j++) {
        float wv = __ldg(&d_w3T[j*128 + o]);
        const float4* row = (const float4*)&s_in[j*20];
#pragma unroll
        for (int q = 0; q < 4; q++) {
            float4 v = row[q];
            a[4*q+0] += v.x*wv; a[4*q+1] += v.y*wv;
            a[4*q+2] += v.z*wv; a[4*q+3] += v.w*wv;
        }
    }
    float mx = 0.f;
#pragma unroll
    for (int k = 0; k < KK2; k++) mx = fmaxf(mx, fmaxf(a[k], 0.f));
    d_lpf[g*128 + o] = mx;
}

// ================= final: ReLU(concat(768) @ Wnew^T + bnew) -> (B,256,M) =====
__global__ void __launch_bounds__(256) final_kernel(const float* __restrict__ Wnew,
                                                    const float* __restrict__ bnew,
                                                    float* __restrict__ out) {
    int g0 = blockIdx.x * 8;
    int tid = threadIdx.x;
    __shared__ float XT[768*8];   // [j][p]
    for (int e = tid; e < 8*128; e += 256) {
        int p = e >> 7, c = e & 127, g = g0 + p;
        float v = d_cfea2[g*128 + c];
        XT[c*8 + p] = v;                    // g_fea3 == c_fea2
        XT[(384+c)*8 + p] = v;              // c_fea2
        XT[(128+c)*8 + p] = d_lpf[g*128 + c];
        XT[(256+c)*8 + p] = d_gfea2[g*128 + c];
    }
    for (int e = tid; e < 8*96; e += 256) {
        int p = e / 96, c = e - p*96, g = g0 + p;
        XT[(512+c)*8 + p] = d_gfea1[g*96 + c];
        XT[(608+c)*8 + p] = d_cfea1[g*96 + c];
    }
    for (int e = tid; e < 8*64; e += 256) {
        int p = e >> 6, c = e & 63, g = g0 + p;
        XT[(704+c)*8 + p] = d_center[g*64 + c];
    }
    __syncthreads();

    int o = tid;
    float acc[8];
    float bv = bnew[o];
#pragma unroll
    for (int p = 0; p < 8; p++) acc[p] = bv;
    const float* wr = Wnew + o*768;
#pragma unroll 4
    for (int j = 0; j < 768; j++) {
        float wv = __ldg(wr + j);
        float4 v0 = *(const float4*)&XT[j*8];
        float4 v1 = *(const float4*)&XT[j*8 + 4];
        acc[0] += v0.x*wv; acc[1] += v0.y*wv; acc[2] += v0.z*wv; acc[3] += v0.w*wv;
        acc[4] += v1.x*wv; acc[5] += v1.y*wv; acc[6] += v1.z*wv; acc[7] += v1.w*wv;
    }
#pragma unroll
    for (int p = 0; p < 8; p++) {
        int g = g0 + p, b = g >> 10, m = g & 1023;
        out[BB*MM*3 + b*256*MM + o*MM + m] = fmaxf(acc[p], 0.f);
    }
}

extern "C" void kernel_launch(void* const* d_in, const int* in_sizes, int n_in,
                              void* d_out, int out_size) {
    const float* xyz      = (const float*)d_in[0];
    const float* features = (const float*)d_in[1];
    const int*   comp     = (const int*)d_in[2];
    const float* W1d  = (const float*)d_in[3];
    const float* b1d  = (const float*)d_in[4];
    const float* Wdx1 = (const float*)d_in[5];
    const float* bdx1 = (const float*)d_in[6];
    const float* Ww1  = (const float*)d_in[7];
    const float* bw1  = (const float*)d_in[8];
    const float* Wdx2 = (const float*)d_in[9];
    const float* bdx2 = (const float*)d_in[10];
    const float* Ww2  = (const float*)d_in[11];
    const float* bw2  = (const float*)d_in[12];
    // d_in[13], d_in[14] = Ww3, bw3 — unused (stage-3 attention is the identity)
    const float* Wsp3 = (const float*)d_in[15];
    const float* bsp3 = (const float*)d_in[16];
    const float* Wnew = (const float*)d_in[17];
    const float* bnew = (const float*)d_in[18];
    float* out = (float*)d_out;

    static const int SMF = NN * 16;                      // 65536 B (fps coords)
    cudaFuncSetAttribute(fps_kernel, cudaFuncAttributeMaxDynamicSharedMemorySize, SMF);

    // order: prep first (independent); feat1 in profile slot 4
    prep_kernel<<<(128*131 + 255)/256, 256>>>(Ww1, Ww2, Wsp3);
    fps_kernel<<<BB, 1024, SMF>>>(xyz, comp, out);        // includes fused gather
    knn1_kernel<<<BB*MM, 256>>>(xyz);
    feat1_kernel<<<BB*NN/4, 256>>>(features, W1d, b1d);   // profiled this round
    stage1_kernel<<<BB*MM, 96>>>(xyz, Wdx1, bdx1, bw1);
    knn2_kernel<<<BB*MM, 256>>>();
    stage2_kernel<<<BB*MM, 128>>>(Wdx2, bdx2, bw2);
    stage3b_kernel<<<BB*MM, 128>>>(bsp3);
    final_kernel<<<BB*MM/8, 256>>>(Wnew, bnew, out);
}